// round 10
// baseline (speedup 1.0000x reference)
#include <cuda_runtime.h>
#include <cstdint>
#include <math.h>

#define BB 32
#define LD 256
#define LP 1024
#define NH 8

// ---- scratch (device globals; allocations forbidden) ----
__device__ float g_rd [(size_t)BB*LD*512];     // rounded drug
__device__ float g_rp [(size_t)BB*LP*512];     // rounded protein
__device__ float g_W  [(size_t)8*512*512];     // rounded weights
__device__ float g_QKd[(size_t)256*LD*128];    // [bh][q][Qd|Kd] scaled, rounded
__device__ float g_KQp[(size_t)256*LP*128];    // [bh][p][Kp|Qp] rounded
__device__ float g_Vd [(size_t)256*LD*64];     // rounded
__device__ float g_Vp [(size_t)256*LP*64];     // rounded
__device__ float g_cd [(size_t)BB*LD*512];     // rounded ctx_d
__device__ float g_cp [(size_t)BB*LP*512];     // rounded ctx_p

__device__ __forceinline__ float rtf(float x){
    uint32_t u = __float_as_uint(x);
    return __uint_as_float((u + 0x1000u) & 0xFFFFE000u);
}
__device__ __forceinline__ void cp16(void* s, const void* g){
    uint32_t sa = (uint32_t)__cvta_generic_to_shared(s);
    asm volatile("cp.async.cg.shared.global [%0], [%1], 16;\n" :: "r"(sa), "l"(g));
}
#define CP_COMMIT asm volatile("cp.async.commit_group;\n")
#define CP_WAIT0  asm volatile("cp.async.wait_group 0;\n")
#define CP_WAIT1  asm volatile("cp.async.wait_group 1;\n")

__device__ __forceinline__ void mma8(float* c, const uint32_t* a, uint32_t b0, uint32_t b1){
    asm volatile("mma.sync.aligned.m16n8k8.row.col.f32.tf32.tf32.f32 "
        "{%0,%1,%2,%3}, {%4,%5,%6,%7}, {%8,%9}, {%0,%1,%2,%3};\n"
        : "+f"(c[0]), "+f"(c[1]), "+f"(c[2]), "+f"(c[3])
        : "r"(a[0]), "r"(a[1]), "r"(a[2]), "r"(a[3]), "r"(b0), "r"(b1));
}
__device__ __forceinline__ float fexp(float x){
    x = fmaxf(x, -80.0f);
    float t = x * 1.44269504089f;
    float n = rintf(t);
    float f = t - n;
    float p =           1.33336621e-3f;
    p = fmaf(p, f, 9.61011902e-3f);
    p = fmaf(p, f, 5.55036420e-2f);
    p = fmaf(p, f, 2.40226522e-1f);
    p = fmaf(p, f, 6.93147182e-1f);
    p = fmaf(p, f, 1.0f);
    return __int_as_float(__float_as_int(p) + ((int)n << 23));
}

// ---- merged tf32 pre-rounding pass: 10 segments in one launch ----
struct Segs {
    const float4* s[10];
    float4*       d[10];
    int           n4[10];
};
__global__ void rnd_all(Segs g){
    const int y = blockIdx.y;
    const float4* src = g.s[y];
    float4*       dst = g.d[y];
    const int n4 = g.n4[y];
    for (int i = blockIdx.x*blockDim.x + threadIdx.x; i < n4; i += gridDim.x*blockDim.x){
        float4 v = src[i];
        v.x = rtf(v.x); v.y = rtf(v.y); v.z = rtf(v.z); v.w = rtf(v.w);
        dst[i] = v;
    }
}

// ---------------------------------------------------------------------------
// TF32 GEMM, cp.async 2-stage double buffer, BK=32, dynamic smem (72KB).
// Single-sync pipeline: {wait0; sync; issue(kt+1); commit; mma(kt)}.
// smem [m][36]: fragment banks 4*(t>>2)+(t&3) -> conflict-free.
// ---------------------------------------------------------------------------
#define STG32 4608   // floats per 128x36 stage
__global__ void __launch_bounds__(256) gemm_ca(
    const float* __restrict__ A, const float* __restrict__ B,
    const float* __restrict__ bias, float* __restrict__ out,
    const float* __restrict__ alphap,
    int Kdim, long long sA, long long sB, long long sO,
    int fmode, int outMode, int L, int ldo, int ostride, int ooff, int roundOut)
{
    extern __shared__ float sm[];
    float* smA = sm;                 // [2][STG32]
    float* smB = sm + 2*STG32;       // [2][STG32]
    const int z = blockIdx.z;
    A += (size_t)z * sA;  B += (size_t)z * sB;  out += (size_t)z * sO;

    const int tid = threadIdx.x, w = tid >> 5, t = tid & 31;
    const int wm = w & 1, wn = w >> 1;
    const int m0 = blockIdx.y * 128, n0 = blockIdx.x * 128;
    const int NK = Kdim >> 5;

    auto issue = [&](int kt, int s){
        float* dA = smA + s*STG32;
        float* dB = smB + s*STG32;
#pragma unroll
        for (int c = tid; c < 1024; c += 256){
            int m = c >> 3, kc = (c & 7) << 2;
            cp16(dA + m*36 + kc, A + (size_t)(m0+m)*Kdim + kt*32 + kc);
        }
#pragma unroll
        for (int c = tid; c < 1024; c += 256){
            int n = c >> 3, kc = (c & 7) << 2;
            cp16(dB + n*36 + kc, B + (size_t)(n0+n)*Kdim + kt*32 + kc);
        }
    };

    issue(0, 0); CP_COMMIT;

    float acc[4][4][4] = {};
    for (int kt = 0; kt < NK; kt++){
        CP_WAIT0;
        __syncthreads();
        if (kt + 1 < NK) issue(kt + 1, (kt + 1) & 1);
        CP_COMMIT;
        const float* cA = smA + (kt & 1)*STG32;
        const float* cB = smB + (kt & 1)*STG32;
#pragma unroll
        for (int kk = 0; kk < 4; kk++){
            const int k0 = kk*8 + (t & 3);
            uint32_t af[4][4];
#pragma unroll
            for (int mt = 0; mt < 4; mt++){
                int r = wm*64 + mt*16 + (t >> 2);
                af[mt][0] = __float_as_uint(cA[ r     *36 + k0    ]);
                af[mt][1] = __float_as_uint(cA[(r + 8)*36 + k0    ]);
                af[mt][2] = __float_as_uint(cA[ r     *36 + k0 + 4]);
                af[mt][3] = __float_as_uint(cA[(r + 8)*36 + k0 + 4]);
            }
#pragma unroll
            for (int nt = 0; nt < 4; nt++){
                int n = wn*32 + nt*8 + (t >> 2);
                uint32_t b0 = __float_as_uint(cB[n*36 + k0    ]);
                uint32_t b1 = __float_as_uint(cB[n*36 + k0 + 4]);
#pragma unroll
                for (int mt = 0; mt < 4; mt++) mma8(acc[mt][nt], af[mt], b0, b1);
            }
        }
    }

    float f = 1.0f;
    if (fmode){
        float a = 1.0f / (1.0f + expf(-alphap[0]));
        f = (fmode == 1 ? a : 1.0f - a) * 0.125f;
    }
#pragma unroll
    for (int mt = 0; mt < 4; mt++){
#pragma unroll
        for (int nt = 0; nt < 4; nt++){
            int gn = n0 + wn*32 + nt*8 + (t & 3)*2;
            float bi0 = bias ? bias[gn]   : 0.0f;
            float bi1 = bias ? bias[gn+1] : 0.0f;
#pragma unroll
            for (int hh = 0; hh < 2; hh++){
                int gm = m0 + wm*64 + mt*16 + (t >> 2) + hh*8;
                float o0 = f * (acc[mt][nt][hh*2  ] + bi0);
                float o1 = f * (acc[mt][nt][hh*2+1] + bi1);
                if (roundOut){ o0 = rtf(o0); o1 = rtf(o1); }
                size_t idx;
                if (outMode == 0) idx = (size_t)gm * ldo + gn;
                else {
                    int b = gm / L, l = gm - b * L;
                    idx = ((size_t)((b*NH + (gn >> 6)) * L + l)) * ostride + ooff + (gn & 63);
                }
                *(float2*)&out[idx] = make_float2(o0, o1);
            }
        }
    }
}

// ---------------------------------------------------------------------------
// Row softmax over 1024 elems, in-place, exact output only (no MUFU).
// ---------------------------------------------------------------------------
__global__ void __launch_bounds__(256) softmax_kernel(
    const float* __restrict__ S, float* __restrict__ out)
{
    const size_t row = blockIdx.x;
    const float* src = S + row * LP;
    float* dst = out + row * LP;
    const int tid = threadIdx.x;

    float4 v = *(const float4*)(src + tid*4);
    float m = fmaxf(fmaxf(v.x, v.y), fmaxf(v.z, v.w));
#pragma unroll
    for (int o = 16; o > 0; o >>= 1) m = fmaxf(m, __shfl_xor_sync(0xFFFFFFFFu, m, o));

    __shared__ float redm[8], reds[8];
    if ((tid & 31) == 0) redm[tid >> 5] = m;
    __syncthreads();
    float rm = redm[0];
#pragma unroll
    for (int i = 1; i < 8; i++) rm = fmaxf(rm, redm[i]);

    float e0 = fexp(v.x - rm), e1 = fexp(v.y - rm);
    float e2 = fexp(v.z - rm), e3 = fexp(v.w - rm);
    float s = e0 + e1 + e2 + e3;
#pragma unroll
    for (int o = 16; o > 0; o >>= 1) s += __shfl_xor_sync(0xFFFFFFFFu, s, o);
    if ((tid & 31) == 0) reds[tid >> 5] = s;
    __syncthreads();
    float tot = 0.0f;
#pragma unroll
    for (int i = 0; i < 8; i++) tot += reds[i];
    float inv = 1.0f / tot;
    *(float4*)(dst + tid*4) = make_float4(e0*inv, e1*inv, e2*inv, e3*inv);
}

// ---------------------------------------------------------------------------
// ctx TF32 cp.async 3-stage (static smem, BK=16). A = exact attn from d_out.
// ---------------------------------------------------------------------------
template<int TRANSA>
__global__ void __launch_bounds__(256) ctx_ca(
    const float* __restrict__ attn, const float* __restrict__ V,
    float* __restrict__ out, int Kdim, int Lout)
{
    const int ASZ = TRANSA ? 2176 : 2560;
    __shared__ float sm[3*2560 + 3*1152];
    float* smB = sm + 3*ASZ;

    const int z = blockIdx.z, b = z >> 3, h = z & 7;
    const int m0 = blockIdx.y * 128;
    const float* A  = attn + (size_t)z * LD * LP;
    const float* Vb = V    + (size_t)z * Kdim * 64;

    const int tid = threadIdx.x, w = tid >> 5, t = tid & 31;
    const int wm = w & 1, wn = w >> 1;
    const int NK = Kdim >> 4;

    auto issue = [&](int kt, int s){
        if (TRANSA == 0){
#pragma unroll
            for (int c = tid; c < 512; c += 256){
                int m = c >> 2, kc = (c & 3) << 2;
                cp16(sm + s*ASZ + m*20 + kc, A + (size_t)(m0+m)*LP + kt*16 + kc);
            }
        } else {
#pragma unroll
            for (int c = tid; c < 512; c += 256){
                int k = c >> 5, m4 = (c & 31) << 2;
                cp16(sm + s*ASZ + k*136 + m4, A + (size_t)(kt*16 + k)*LP + m0 + m4);
            }
        }
        { int c = tid; int k = c >> 4, cc = (c & 15) << 2;
          cp16(smB + s*1152 + k*72 + cc, Vb + (size_t)(kt*16 + k)*64 + cc); }
    };

    issue(0, 0); CP_COMMIT;
    issue(1, 1); CP_COMMIT;

    float acc[4][2][4] = {};
    for (int kt = 0; kt < NK; kt++){
        CP_WAIT1;
        __syncthreads();
        if (kt + 2 < NK) issue(kt + 2, (kt + 2) % 3);
        CP_COMMIT;
        const float* cA = sm + (kt % 3) * ASZ;
        const float* cB = smB + (kt % 3) * 1152;
#pragma unroll
        for (int kk = 0; kk < 2; kk++){
            const int k0 = kk*8 + (t & 3);
            uint32_t af[4][4];
#pragma unroll
            for (int mt = 0; mt < 4; mt++){
                int r = wm*64 + mt*16 + (t >> 2);
                if (TRANSA == 0){
                    af[mt][0] = __float_as_uint(cA[ r     *20 + k0    ]);
                    af[mt][1] = __float_as_uint(cA[(r + 8)*20 + k0    ]);
                    af[mt][2] = __float_as_uint(cA[ r     *20 + k0 + 4]);
                    af[mt][3] = __float_as_uint(cA[(r + 8)*20 + k0 + 4]);
                } else {
                    af[mt][0] = __float_as_uint(cA[ k0     *136 + r    ]);
                    af[mt][1] = __float_as_uint(cA[ k0     *136 + r + 8]);
                    af[mt][2] = __float_as_uint(cA[(k0 + 4)*136 + r    ]);
                    af[mt][3] = __float_as_uint(cA[(k0 + 4)*136 + r + 8]);
                }
            }
#pragma unroll
            for (int nt = 0; nt < 2; nt++){
                int n = wn*16 + nt*8 + (t >> 2);
                uint32_t b0 = __float_as_uint(cB[ k0     *72 + n]);
                uint32_t b1 = __float_as_uint(cB[(k0 + 4)*72 + n]);
#pragma unroll
                for (int mt = 0; mt < 4; mt++) mma8(acc[mt][nt], af[mt], b0, b1);
            }
        }
    }

#pragma unroll
    for (int mt = 0; mt < 4; mt++){
#pragma unroll
        for (int nt = 0; nt < 2; nt++){
            int gn = wn*16 + nt*8 + (t & 3)*2;
#pragma unroll
            for (int hh = 0; hh < 2; hh++){
                int gm = m0 + wm*64 + mt*16 + (t >> 2) + hh*8;
                size_t idx = ((size_t)(b*Lout + gm))*512 + h*64 + gn;
                *(float2*)&out[idx] = make_float2(rtf(acc[mt][nt][hh*2]), rtf(acc[mt][nt][hh*2+1]));
            }
        }
    }
}

// ---------------------------------------------------------------------------
extern "C" void kernel_launch(void* const* d_in, const int* in_sizes, int n_in,
                              void* d_out, int out_size) {
    const float* drug    = (const float*)d_in[0];
    const float* protein = (const float*)d_in[1];
    const float* Wqd = (const float*)d_in[2];  const float* bqd = (const float*)d_in[3];
    const float* Wkp = (const float*)d_in[4];  const float* bkp = (const float*)d_in[5];
    const float* Wvp = (const float*)d_in[6];  const float* bvp = (const float*)d_in[7];
    const float* Wqp = (const float*)d_in[8];  const float* bqp = (const float*)d_in[9];
    const float* Wkd = (const float*)d_in[10]; const float* bkd = (const float*)d_in[11];
    const float* Wvd = (const float*)d_in[12]; const float* bvd = (const float*)d_in[13];
    const float* alpha = (const float*)d_in[14];
    const float* Wod = (const float*)d_in[15]; const float* bod = (const float*)d_in[16];
    const float* Wop = (const float*)d_in[17]; const float* bop = (const float*)d_in[18];

    float* out      = (float*)d_out;
    float* out_attn = out;
    float* out_cd   = out + (size_t)256*LD*LP;
    float* out_cp   = out_cd + (size_t)BB*LD*512;

    float *rd, *rp, *rw, *qkd, *kqp, *vd, *vp, *cd, *cp;
    cudaGetSymbolAddress((void**)&rd,  g_rd);
    cudaGetSymbolAddress((void**)&rp,  g_rp);
    cudaGetSymbolAddress((void**)&rw,  g_W);
    cudaGetSymbolAddress((void**)&qkd, g_QKd);
    cudaGetSymbolAddress((void**)&kqp, g_KQp);
    cudaGetSymbolAddress((void**)&vd,  g_Vd);
    cudaGetSymbolAddress((void**)&vp,  g_Vp);
    cudaGetSymbolAddress((void**)&cd,  g_cd);
    cudaGetSymbolAddress((void**)&cp,  g_cp);

    cudaFuncSetAttribute(gemm_ca, cudaFuncAttributeMaxDynamicSharedMemorySize, 73728);

    const int WSZ = 512*512, W4 = WSZ/4;
    // Single merged rounding launch (10 segments).
    Segs sg;
    const float* Ws[8] = {Wqd, Wkd, Wvd, Wkp, Wqp, Wvp, Wod, Wop};
    sg.s[0] = (const float4*)drug;    sg.d[0] = (float4*)rd; sg.n4[0] = BB*LD*512/4;
    sg.s[1] = (const float4*)protein; sg.d[1] = (float4*)rp; sg.n4[1] = BB*LP*512/4;
    for (int i = 0; i < 8; i++){
        sg.s[2+i] = (const float4*)Ws[i];
        sg.d[2+i] = (float4*)(rw + (size_t)i*WSZ);
        sg.n4[2+i] = W4;
    }
    rnd_all<<<dim3(512, 10), 256>>>(sg);

    // Projections (rounded outputs). Qd: sig(a)/8; Kd: (1-sig(a))/8.
    gemm_ca<<<dim3(4,64),  256, 73728>>>(rd, rw + 0*WSZ, bqd, qkd, alpha, 512,0,0,0, 1,1, LD, 0, 128, 0, 1);
    gemm_ca<<<dim3(4,64),  256, 73728>>>(rd, rw + 1*WSZ, bkd, qkd, alpha, 512,0,0,0, 2,1, LD, 0, 128, 64, 1);
    gemm_ca<<<dim3(4,64),  256, 73728>>>(rd, rw + 2*WSZ, bvd, vd,  alpha, 512,0,0,0, 0,1, LD, 0, 64, 0, 1);
    gemm_ca<<<dim3(4,256), 256, 73728>>>(rp, rw + 3*WSZ, bkp, kqp, alpha, 512,0,0,0, 0,1, LP, 0, 128, 0, 1);
    gemm_ca<<<dim3(4,256), 256, 73728>>>(rp, rw + 4*WSZ, bqp, kqp, alpha, 512,0,0,0, 0,1, LP, 0, 128, 64, 1);
    gemm_ca<<<dim3(4,256), 256, 73728>>>(rp, rw + 5*WSZ, bvp, vp,  alpha, 512,0,0,0, 0,1, LP, 0, 64, 0, 1);

    // Scores: [Qd|Kd]@[Kp|Qp]^T, K=128, exact into attn region; softmax in place.
    gemm_ca<<<dim3(8,2,256), 256, 73728>>>(qkd, kqp, nullptr, out_attn, alpha,
                                           128, (long long)LD*128, (long long)LP*128,
                                           (long long)LD*LP, 0,0, LD, LP, 0, 0, 0);
    softmax_kernel<<<256*LD, 256>>>(out_attn, out_attn);

    // Contexts read exact attn from d_out (HW tf32 truncation); V pre-rounded.
    ctx_ca<0><<<dim3(1,2,256), 256>>>(out_attn, vp, cd, LP, LD);
    ctx_ca<1><<<dim3(1,8,256), 256>>>(out_attn, vd, cp, LD, LP);

    // Output projections (exact into d_out).
    gemm_ca<<<dim3(4,64),  256, 73728>>>(cd, rw + 6*WSZ, bod, out_cd, alpha, 512,0,0,0, 0,0, LD, 512, 0, 0, 0);
    gemm_ca<<<dim3(4,256), 256, 73728>>>(cp, rw + 7*WSZ, bop, out_cp, alpha, 512,0,0,0, 0,0, LP, 512, 0, 0, 0);
}

// round 11
// speedup vs baseline: 1.0403x; 1.0403x over previous
#include <cuda_runtime.h>
#include <cstdint>
#include <math.h>

#define BB 32
#define LD 256
#define LP 1024
#define NH 8

// ---- scratch (device globals; allocations forbidden) ----
// All gemm-consumed buffers use a k-interleaved layout: within each 16-wide
// k-block, element k sits at position (k%4)*4 + k/4. A thread's 4 needed
// k-values {q,q+4,q+8,q+12} are then contiguous -> LDS.128 fragments.
__device__ float g_rd [(size_t)BB*LD*512];     // rounded drug (perm)
__device__ float g_rp [(size_t)BB*LP*512];     // rounded protein (perm)
__device__ float g_W  [(size_t)8*512*512];     // rounded weights (perm)
__device__ float g_QKd[(size_t)256*LD*128];    // [bh][q][Qd|Kd] scaled (perm)
__device__ float g_KQp[(size_t)256*LP*128];    // [bh][p][Kp|Qp] (perm)
__device__ float g_Vd [(size_t)256*LD*64];     // rounded (UNperm; ctx B)
__device__ float g_Vp [(size_t)256*LP*64];     // rounded (UNperm; ctx B)
__device__ float g_cd [(size_t)BB*LD*512];     // ctx_d (perm)
__device__ float g_cp [(size_t)BB*LP*512];     // ctx_p (perm)

__device__ __forceinline__ float rtf(float x){
    uint32_t u = __float_as_uint(x);
    return __uint_as_float((u + 0x1000u) & 0xFFFFE000u);
}
__device__ __forceinline__ void cp16(void* s, const void* g){
    uint32_t sa = (uint32_t)__cvta_generic_to_shared(s);
    asm volatile("cp.async.cg.shared.global [%0], [%1], 16;\n" :: "r"(sa), "l"(g));
}
#define CP_COMMIT asm volatile("cp.async.commit_group;\n")
#define CP_WAIT0  asm volatile("cp.async.wait_group 0;\n")
#define CP_WAIT1  asm volatile("cp.async.wait_group 1;\n")

__device__ __forceinline__ void mma8(float* c, uint32_t a0, uint32_t a1,
                                     uint32_t a2, uint32_t a3, uint32_t b0, uint32_t b1){
    asm volatile("mma.sync.aligned.m16n8k8.row.col.f32.tf32.tf32.f32 "
        "{%0,%1,%2,%3}, {%4,%5,%6,%7}, {%8,%9}, {%0,%1,%2,%3};\n"
        : "+f"(c[0]), "+f"(c[1]), "+f"(c[2]), "+f"(c[3])
        : "r"(a0), "r"(a1), "r"(a2), "r"(a3), "r"(b0), "r"(b1));
}
__device__ __forceinline__ float fexp(float x){
    x = fmaxf(x, -80.0f);
    float t = x * 1.44269504089f;
    float n = rintf(t);
    float f = t - n;
    float p =           1.33336621e-3f;
    p = fmaf(p, f, 9.61011902e-3f);
    p = fmaf(p, f, 5.55036420e-2f);
    p = fmaf(p, f, 2.40226522e-1f);
    p = fmaf(p, f, 6.93147182e-1f);
    p = fmaf(p, f, 1.0f);
    return __int_as_float(__float_as_int(p) + ((int)n << 23));
}

// ---- merged tf32 pre-rounding + k-interleave pass (rows are 512 wide) ----
struct Segs {
    const float4* s[10];
    float*        d[10];
    int           n4[10];
};
__global__ void rnd_all(Segs g){
    const int y = blockIdx.y;
    const float4* src = g.s[y];
    float*        dst = g.d[y];
    const int n4 = g.n4[y];
    for (int i = blockIdx.x*blockDim.x + threadIdx.x; i < n4; i += gridDim.x*blockDim.x){
        float4 v = src[i];
        long long flat = (long long)i * 4;
        int c0 = (int)(flat & 511);              // column (row len 512)
        long long rowbase = flat - c0;
        int blk = c0 & ~15, a = (c0 >> 2) & 3;   // c0 % 16 = 4a
        float* d = dst + rowbase + blk;
        d[a     ] = rtf(v.x);
        d[a + 4 ] = rtf(v.y);
        d[a + 8 ] = rtf(v.z);
        d[a + 12] = rtf(v.w);
    }
}

// ---------------------------------------------------------------------------
// TF32 GEMM, cp.async 2-stage, BK=16, static smem 32KB, 2 blocks/SM.
// Operands in k-interleaved layout -> all fragments via LDS.128, stride-16
// rows (no padding), bank-conflict-free (quads 0..7 per phase).
// permOut: epilogue writes columns k-interleaved (for gemm-consumed outputs).
// ---------------------------------------------------------------------------
__global__ void __launch_bounds__(256,2) gemm_ca(
    const float* __restrict__ A, const float* __restrict__ B,
    const float* __restrict__ bias, float* __restrict__ out,
    const float* __restrict__ alphap,
    int Kdim, long long sA, long long sB, long long sO,
    int fmode, int outMode, int L, int ldo, int ostride, int ooff,
    int roundOut, int permOut)
{
    __shared__ float smA[2][2048];
    __shared__ float smB[2][2048];
    const int z = blockIdx.z;
    A += (size_t)z * sA;  B += (size_t)z * sB;  out += (size_t)z * sO;

    const int tid = threadIdx.x, w = tid >> 5, t = tid & 31;
    const int wm = w & 1, wn = w >> 1;
    const int m0 = blockIdx.y * 128, n0 = blockIdx.x * 128;
    const int NK = Kdim >> 4;
    const int q4 = (t & 3) << 2;
    const int r4 = t >> 2;

    auto issue = [&](int kt, int s){
#pragma unroll
        for (int c = tid; c < 512; c += 256){
            int m = c >> 2, kc = (c & 3) << 2;
            cp16(&smA[s][m*16 + kc], A + (size_t)(m0+m)*Kdim + kt*16 + kc);
        }
#pragma unroll
        for (int c = tid; c < 512; c += 256){
            int n = c >> 2, kc = (c & 3) << 2;
            cp16(&smB[s][n*16 + kc], B + (size_t)(n0+n)*Kdim + kt*16 + kc);
        }
    };

    issue(0, 0); CP_COMMIT;

    float acc[4][4][4] = {};
    for (int kt = 0; kt < NK; kt++){
        CP_WAIT0;
        __syncthreads();
        if (kt + 1 < NK) issue(kt + 1, (kt + 1) & 1);
        CP_COMMIT;
        const float* cA = smA[kt & 1];
        const float* cB = smB[kt & 1];

        float4 a4[4][2], b4[4];
#pragma unroll
        for (int mt = 0; mt < 4; mt++){
            int r = wm*64 + mt*16 + r4;
            a4[mt][0] = *(const float4*)&cA[ r     *16 + q4];
            a4[mt][1] = *(const float4*)&cA[(r + 8)*16 + q4];
        }
#pragma unroll
        for (int nt = 0; nt < 4; nt++){
            int n = wn*32 + nt*8 + r4;
            b4[nt] = *(const float4*)&cB[n*16 + q4];
        }
        // kk=0: k = q, q+4 -> .x/.y ; kk=1: k = q+8, q+12 -> .z/.w
#pragma unroll
        for (int nt = 0; nt < 4; nt++){
            uint32_t b0 = __float_as_uint(b4[nt].x), b1 = __float_as_uint(b4[nt].y);
#pragma unroll
            for (int mt = 0; mt < 4; mt++)
                mma8(acc[mt][nt],
                     __float_as_uint(a4[mt][0].x), __float_as_uint(a4[mt][1].x),
                     __float_as_uint(a4[mt][0].y), __float_as_uint(a4[mt][1].y), b0, b1);
        }
#pragma unroll
        for (int nt = 0; nt < 4; nt++){
            uint32_t b0 = __float_as_uint(b4[nt].z), b1 = __float_as_uint(b4[nt].w);
#pragma unroll
            for (int mt = 0; mt < 4; mt++)
                mma8(acc[mt][nt],
                     __float_as_uint(a4[mt][0].z), __float_as_uint(a4[mt][1].z),
                     __float_as_uint(a4[mt][0].w), __float_as_uint(a4[mt][1].w), b0, b1);
        }
    }

    float f = 1.0f;
    if (fmode){
        float a = 1.0f / (1.0f + expf(-alphap[0]));
        f = (fmode == 1 ? a : 1.0f - a) * 0.125f;
    }
#pragma unroll
    for (int mt = 0; mt < 4; mt++){
#pragma unroll
        for (int nt = 0; nt < 4; nt++){
            int gn = n0 + wn*32 + nt*8 + (t & 3)*2;
            float bi0 = bias ? bias[gn]   : 0.0f;
            float bi1 = bias ? bias[gn+1] : 0.0f;
#pragma unroll
            for (int hh = 0; hh < 2; hh++){
                int gm = m0 + wm*64 + mt*16 + (t >> 2) + hh*8;
                float o0 = f * (acc[mt][nt][hh*2  ] + bi0);
                float o1 = f * (acc[mt][nt][hh*2+1] + bi1);
                if (roundOut){ o0 = rtf(o0); o1 = rtf(o1); }
                if (outMode == 0){
                    *(float2*)&out[(size_t)gm * ldo + gn] = make_float2(o0, o1);
                } else {
                    int b = gm / L, l = gm - b * L;
                    size_t rowb = ((size_t)((b*NH + (gn >> 6)) * L + l)) * ostride;
                    int c = ooff + (gn & 63);
                    if (permOut){
                        int bb = c & 15;
                        int p0 = (bb & 3)*4 + (bb >> 2);   // even bb: pos(b+1)=pos(b)+4
                        out[rowb + (c & ~15) + p0    ] = o0;
                        out[rowb + (c & ~15) + p0 + 4] = o1;
                    } else {
                        *(float2*)&out[rowb + c] = make_float2(o0, o1);
                    }
                }
            }
        }
    }
}

// ---------------------------------------------------------------------------
// Row softmax over 1024 elems, in-place, exact output only (no MUFU).
// ---------------------------------------------------------------------------
__global__ void __launch_bounds__(256) softmax_kernel(
    const float* __restrict__ S, float* __restrict__ out)
{
    const size_t row = blockIdx.x;
    const float* src = S + row * LP;
    float* dst = out + row * LP;
    const int tid = threadIdx.x;

    float4 v = *(const float4*)(src + tid*4);
    float m = fmaxf(fmaxf(v.x, v.y), fmaxf(v.z, v.w));
#pragma unroll
    for (int o = 16; o > 0; o >>= 1) m = fmaxf(m, __shfl_xor_sync(0xFFFFFFFFu, m, o));

    __shared__ float redm[8], reds[8];
    if ((tid & 31) == 0) redm[tid >> 5] = m;
    __syncthreads();
    float rm = redm[0];
#pragma unroll
    for (int i = 1; i < 8; i++) rm = fmaxf(rm, redm[i]);

    float e0 = fexp(v.x - rm), e1 = fexp(v.y - rm);
    float e2 = fexp(v.z - rm), e3 = fexp(v.w - rm);
    float s = e0 + e1 + e2 + e3;
#pragma unroll
    for (int o = 16; o > 0; o >>= 1) s += __shfl_xor_sync(0xFFFFFFFFu, s, o);
    if ((tid & 31) == 0) reds[tid >> 5] = s;
    __syncthreads();
    float tot = 0.0f;
#pragma unroll
    for (int i = 0; i < 8; i++) tot += reds[i];
    float inv = 1.0f / tot;
    *(float4*)(dst + tid*4) = make_float4(e0*inv, e1*inv, e2*inv, e3*inv);
}

// ---------------------------------------------------------------------------
// ctx TF32 cp.async 3-stage (static smem, BK=16), UNpermuted operands.
// A = exact attn (d_out); B = Vd/Vp. Output cd/cp written k-interleaved
// (consumed by the final gemm_ca projections).
// ---------------------------------------------------------------------------
template<int TRANSA>
__global__ void __launch_bounds__(256) ctx_ca(
    const float* __restrict__ attn, const float* __restrict__ V,
    float* __restrict__ out, int Kdim, int Lout)
{
    const int ASZ = TRANSA ? 2176 : 2560;
    __shared__ float sm[3*2560 + 3*1152];
    float* smB = sm + 3*ASZ;

    const int z = blockIdx.z, b = z >> 3, h = z & 7;
    const int m0 = blockIdx.y * 128;
    const float* A  = attn + (size_t)z * LD * LP;
    const float* Vb = V    + (size_t)z * Kdim * 64;

    const int tid = threadIdx.x, w = tid >> 5, t = tid & 31;
    const int wm = w & 1, wn = w >> 1;
    const int NK = Kdim >> 4;

    auto issue = [&](int kt, int s){
        if (TRANSA == 0){
#pragma unroll
            for (int c = tid; c < 512; c += 256){
                int m = c >> 2, kc = (c & 3) << 2;
                cp16(sm + s*ASZ + m*20 + kc, A + (size_t)(m0+m)*LP + kt*16 + kc);
            }
        } else {
#pragma unroll
            for (int c = tid; c < 512; c += 256){
                int k = c >> 5, m4 = (c & 31) << 2;
                cp16(sm + s*ASZ + k*136 + m4, A + (size_t)(kt*16 + k)*LP + m0 + m4);
            }
        }
        { int c = tid; int k = c >> 4, cc = (c & 15) << 2;
          cp16(smB + s*1152 + k*72 + cc, Vb + (size_t)(kt*16 + k)*64 + cc); }
    };

    issue(0, 0); CP_COMMIT;
    issue(1, 1); CP_COMMIT;

    float acc[4][2][4] = {};
    for (int kt = 0; kt < NK; kt++){
        CP_WAIT1;
        __syncthreads();
        if (kt + 2 < NK) issue(kt + 2, (kt + 2) % 3);
        CP_COMMIT;
        const float* cA = sm + (kt % 3) * ASZ;
        const float* cB = smB + (kt % 3) * 1152;
#pragma unroll
        for (int kk = 0; kk < 2; kk++){
            const int k0 = kk*8 + (t & 3);
            uint32_t af[4][4];
#pragma unroll
            for (int mt = 0; mt < 4; mt++){
                int r = wm*64 + mt*16 + (t >> 2);
                if (TRANSA == 0){
                    af[mt][0] = __float_as_uint(cA[ r     *20 + k0    ]);
                    af[mt][1] = __float_as_uint(cA[(r + 8)*20 + k0    ]);
                    af[mt][2] = __float_as_uint(cA[ r     *20 + k0 + 4]);
                    af[mt][3] = __float_as_uint(cA[(r + 8)*20 + k0 + 4]);
                } else {
                    af[mt][0] = __float_as_uint(cA[ k0     *136 + r    ]);
                    af[mt][1] = __float_as_uint(cA[ k0     *136 + r + 8]);
                    af[mt][2] = __float_as_uint(cA[(k0 + 4)*136 + r    ]);
                    af[mt][3] = __float_as_uint(cA[(k0 + 4)*136 + r + 8]);
                }
            }
#pragma unroll
            for (int nt = 0; nt < 2; nt++){
                int n = wn*16 + nt*8 + (t >> 2);
                uint32_t b0 = __float_as_uint(cB[ k0     *72 + n]);
                uint32_t b1 = __float_as_uint(cB[(k0 + 4)*72 + n]);
#pragma unroll
                for (int mt = 0; mt < 4; mt++)
                    mma8(acc[mt][nt], af[mt][0], af[mt][1], af[mt][2], af[mt][3], b0, b1);
            }
        }
    }

#pragma unroll
    for (int mt = 0; mt < 4; mt++){
#pragma unroll
        for (int nt = 0; nt < 2; nt++){
            int gn = wn*16 + nt*8 + (t & 3)*2;
            int bb = gn & 15;
            int p0 = (bb & 3)*4 + (bb >> 2);
#pragma unroll
            for (int hh = 0; hh < 2; hh++){
                int gm = m0 + wm*64 + mt*16 + (t >> 2) + hh*8;
                size_t base = ((size_t)(b*Lout + gm))*512 + ((h*64 + gn) & ~15);
                out[base + p0    ] = rtf(acc[mt][nt][hh*2  ]);
                out[base + p0 + 4] = rtf(acc[mt][nt][hh*2+1]);
            }
        }
    }
}

// ---------------------------------------------------------------------------
extern "C" void kernel_launch(void* const* d_in, const int* in_sizes, int n_in,
                              void* d_out, int out_size) {
    const float* drug    = (const float*)d_in[0];
    const float* protein = (const float*)d_in[1];
    const float* Wqd = (const float*)d_in[2];  const float* bqd = (const float*)d_in[3];
    const float* Wkp = (const float*)d_in[4];  const float* bkp = (const float*)d_in[5];
    const float* Wvp = (const float*)d_in[6];  const float* bvp = (const float*)d_in[7];
    const float* Wqp = (const float*)d_in[8];  const float* bqp = (const float*)d_in[9];
    const float* Wkd = (const float*)d_in[10]; const float* bkd = (const float*)d_in[11];
    const float* Wvd = (const float*)d_in[12]; const float* bvd = (const float*)d_in[13];
    const float* alpha = (const float*)d_in[14];
    const float* Wod = (const float*)d_in[15]; const float* bod = (const float*)d_in[16];
    const float* Wop = (const float*)d_in[17]; const float* bop = (const float*)d_in[18];

    float* out      = (float*)d_out;
    float* out_attn = out;
    float* out_cd   = out + (size_t)256*LD*LP;
    float* out_cp   = out_cd + (size_t)BB*LD*512;

    float *rd, *rp, *rw, *qkd, *kqp, *vd, *vp, *cd, *cp;
    cudaGetSymbolAddress((void**)&rd,  g_rd);
    cudaGetSymbolAddress((void**)&rp,  g_rp);
    cudaGetSymbolAddress((void**)&rw,  g_W);
    cudaGetSymbolAddress((void**)&qkd, g_QKd);
    cudaGetSymbolAddress((void**)&kqp, g_KQp);
    cudaGetSymbolAddress((void**)&vd,  g_Vd);
    cudaGetSymbolAddress((void**)&vp,  g_Vp);
    cudaGetSymbolAddress((void**)&cd,  g_cd);
    cudaGetSymbolAddress((void**)&cp,  g_cp);

    const int WSZ = 512*512, W4 = WSZ/4;
    // Single merged rounding+interleave launch (10 segments).
    Segs sg;
    const float* Ws[8] = {Wqd, Wkd, Wvd, Wkp, Wqp, Wvp, Wod, Wop};
    sg.s[0] = (const float4*)drug;    sg.d[0] = rd; sg.n4[0] = BB*LD*512/4;
    sg.s[1] = (const float4*)protein; sg.d[1] = rp; sg.n4[1] = BB*LP*512/4;
    for (int i = 0; i < 8; i++){
        sg.s[2+i] = (const float4*)Ws[i];
        sg.d[2+i] = rw + (size_t)i*WSZ;
        sg.n4[2+i] = W4;
    }
    rnd_all<<<dim3(512, 10), 256>>>(sg);

    // Projections. Qd: sig(a)/8; Kd: (1-sig(a))/8. qkd/kqp k-interleaved;
    // vd/vp plain (ctx operands).
    gemm_ca<<<dim3(4,64),  256>>>(rd, rw + 0*WSZ, bqd, qkd, alpha, 512,0,0,0, 1,1, LD, 0, 128, 0,  1,1);
    gemm_ca<<<dim3(4,64),  256>>>(rd, rw + 1*WSZ, bkd, qkd, alpha, 512,0,0,0, 2,1, LD, 0, 128, 64, 1,1);
    gemm_ca<<<dim3(4,64),  256>>>(rd, rw + 2*WSZ, bvd, vd,  alpha, 512,0,0,0, 0,1, LD, 0, 64, 0,  1,0);
    gemm_ca<<<dim3(4,256), 256>>>(rp, rw + 3*WSZ, bkp, kqp, alpha, 512,0,0,0, 0,1, LP, 0, 128, 0,  1,1);
    gemm_ca<<<dim3(4,256), 256>>>(rp, rw + 4*WSZ, bqp, kqp, alpha, 512,0,0,0, 0,1, LP, 0, 128, 64, 1,1);
    gemm_ca<<<dim3(4,256), 256>>>(rp, rw + 5*WSZ, bvp, vp,  alpha, 512,0,0,0, 0,1, LP, 0, 64, 0,  1,0);

    // Scores: [Qd|Kd]@[Kp|Qp]^T, K=128 (interleaved), exact output; softmax in place.
    gemm_ca<<<dim3(8,2,256), 256>>>(qkd, kqp, nullptr, out_attn, alpha,
                                    128, (long long)LD*128, (long long)LP*128,
                                    (long long)LD*LP, 0,0, LD, LP, 0, 0, 0,0);
    softmax_kernel<<<256*LD, 256>>>(out_attn, out_attn);

    // Contexts (unpermuted attn/V); outputs k-interleaved for out-proj.
    ctx_ca<0><<<dim3(1,2,256), 256>>>(out_attn, vp, cd, LP, LD);
    ctx_ca<1><<<dim3(1,8,256), 256>>>(out_attn, vd, cp, LD, LP);

    // Output projections (exact into d_out, plain layout).
    gemm_ca<<<dim3(4,64),  256>>>(cd, rw + 6*WSZ, bod, out_cd, alpha, 512,0,0,0, 0,0, LD, 512, 0, 0, 0,0);
    gemm_ca<<<dim3(4,256), 256>>>(cp, rw + 7*WSZ, bop, out_cp, alpha, 512,0,0,0, 0,0, LP, 512, 0, 0, 0,0);
}

// round 12
// speedup vs baseline: 1.0912x; 1.0489x over previous
#include <cuda_runtime.h>
#include <cstdint>
#include <math.h>

#define BB 32
#define LD 256
#define LP 1024
#define NH 8

// ---- scratch (device globals; allocations forbidden) ----
// k-interleaved layout for gemm-consumed buffers: within each 16-wide k-block,
// element k sits at position (k%4)*4 + k/4 -> LDS.128 fragments.
__device__ float g_rd [(size_t)BB*LD*512];     // rounded drug (perm)
__device__ float g_rp [(size_t)BB*LP*512];     // rounded protein (perm)
__device__ float g_W  [(size_t)8*512*512];     // rounded weights (perm)
__device__ float g_QKd[(size_t)256*LD*128];    // [bh][q][Qd|Kd] scaled (perm)
__device__ float g_KQp[(size_t)256*LP*128];    // [bh][p][Kp|Qp] (perm)
__device__ float g_Vd [(size_t)256*LD*64];     // rounded (UNperm; ctx B)
__device__ float g_Vp [(size_t)256*LP*64];     // rounded (UNperm; ctx B)
__device__ float g_cd [(size_t)BB*LD*512];     // ctx_d (perm)
__device__ float g_cp [(size_t)BB*LP*512];     // ctx_p (perm)

__device__ __forceinline__ float rtf(float x){
    uint32_t u = __float_as_uint(x);
    return __uint_as_float((u + 0x1000u) & 0xFFFFE000u);
}
__device__ __forceinline__ void cp16(void* s, const void* g){
    uint32_t sa = (uint32_t)__cvta_generic_to_shared(s);
    asm volatile("cp.async.cg.shared.global [%0], [%1], 16;\n" :: "r"(sa), "l"(g));
}
#define CP_COMMIT asm volatile("cp.async.commit_group;\n")
#define CP_WAIT1  asm volatile("cp.async.wait_group 1;\n")

__device__ __forceinline__ void mma8(float* c, uint32_t a0, uint32_t a1,
                                     uint32_t a2, uint32_t a3, uint32_t b0, uint32_t b1){
    asm volatile("mma.sync.aligned.m16n8k8.row.col.f32.tf32.tf32.f32 "
        "{%0,%1,%2,%3}, {%4,%5,%6,%7}, {%8,%9}, {%0,%1,%2,%3};\n"
        : "+f"(c[0]), "+f"(c[1]), "+f"(c[2]), "+f"(c[3])
        : "r"(a0), "r"(a1), "r"(a2), "r"(a3), "r"(b0), "r"(b1));
}
__device__ __forceinline__ float fexp(float x){
    x = fmaxf(x, -80.0f);
    float t = x * 1.44269504089f;
    float n = rintf(t);
    float f = t - n;
    float p =           1.33336621e-3f;
    p = fmaf(p, f, 9.61011902e-3f);
    p = fmaf(p, f, 5.55036420e-2f);
    p = fmaf(p, f, 2.40226522e-1f);
    p = fmaf(p, f, 6.93147182e-1f);
    p = fmaf(p, f, 1.0f);
    return __int_as_float(__float_as_int(p) + ((int)n << 23));
}

// ---- merged tf32 pre-rounding + k-interleave pass (rows are 512 wide) ----
struct Segs {
    const float4* s[10];
    float*        d[10];
    int           n4[10];
};
__global__ void rnd_all(Segs g){
    const int y = blockIdx.y;
    const float4* src = g.s[y];
    float*        dst = g.d[y];
    const int n4 = g.n4[y];
    for (int i = blockIdx.x*blockDim.x + threadIdx.x; i < n4; i += gridDim.x*blockDim.x){
        float4 v = src[i];
        long long flat = (long long)i * 4;
        int c0 = (int)(flat & 511);
        long long rowbase = flat - c0;
        int blk = c0 & ~15, a = (c0 >> 2) & 3;
        float* d = dst + rowbase + blk;
        d[a     ] = rtf(v.x);
        d[a + 4 ] = rtf(v.y);
        d[a + 8 ] = rtf(v.z);
        d[a + 12] = rtf(v.w);
    }
}

// ---- shared mainloop helpers (k-interleaved operands, LDS.128 fragments) ---
#define GEMM_MAINLOOP(Aptr, Bptr, Kdim, NK)                                     \
    const int q4 = (t & 3) << 2;                                                \
    const int r4 = t >> 2;                                                      \
    const uint32_t offL = (uint32_t)((tid >> 2)*16 + ((tid & 3) << 2));         \
    const float* ApLo = Aptr + (size_t)(m0 + (tid >> 2))*(Kdim) + ((tid & 3) << 2); \
    const float* ApHi = ApLo + (size_t)64*(Kdim);                               \
    const float* BpLo = Bptr + (size_t)(n0 + (tid >> 2))*(Kdim) + ((tid & 3) << 2); \
    const float* BpHi = BpLo + (size_t)64*(Kdim);                               \
    auto issue = [&](int kt, int s){                                            \
        cp16(&smA[s][offL       ], ApLo + kt*16);                               \
        cp16(&smA[s][offL + 1024], ApHi + kt*16);                               \
        cp16(&smB[s][offL       ], BpLo + kt*16);                               \
        cp16(&smB[s][offL + 1024], BpHi + kt*16);                               \
    };                                                                          \
    issue(0, 0); CP_COMMIT;                                                     \
    issue(1, 1); CP_COMMIT;                                                     \
    float acc[4][4][4] = {};                                                    \
    for (int kt = 0; kt < (NK); kt++){                                          \
        CP_WAIT1;                                                               \
        __syncthreads();                                                        \
        if (kt + 2 < (NK)) issue(kt + 2, (kt + 2) % 3);                         \
        CP_COMMIT;                                                              \
        const float* cA = smA[kt % 3];                                          \
        const float* cB = smB[kt % 3];                                          \
        float4 a4[4][2], b4[4];                                                 \
        _Pragma("unroll")                                                       \
        for (int mt = 0; mt < 4; mt++){                                         \
            int r = wm*64 + mt*16 + r4;                                         \
            a4[mt][0] = *(const float4*)&cA[ r     *16 + q4];                   \
            a4[mt][1] = *(const float4*)&cA[(r + 8)*16 + q4];                   \
        }                                                                       \
        _Pragma("unroll")                                                       \
        for (int nt = 0; nt < 4; nt++){                                         \
            int n = wn*32 + nt*8 + r4;                                          \
            b4[nt] = *(const float4*)&cB[n*16 + q4];                            \
        }                                                                       \
        _Pragma("unroll")                                                       \
        for (int nt = 0; nt < 4; nt++){                                         \
            uint32_t b0 = __float_as_uint(b4[nt].x), b1 = __float_as_uint(b4[nt].y); \
            _Pragma("unroll")                                                   \
            for (int mt = 0; mt < 4; mt++)                                      \
                mma8(acc[mt][nt],                                               \
                     __float_as_uint(a4[mt][0].x), __float_as_uint(a4[mt][1].x),\
                     __float_as_uint(a4[mt][0].y), __float_as_uint(a4[mt][1].y), b0, b1); \
        }                                                                       \
        _Pragma("unroll")                                                       \
        for (int nt = 0; nt < 4; nt++){                                         \
            uint32_t b0 = __float_as_uint(b4[nt].z), b1 = __float_as_uint(b4[nt].w); \
            _Pragma("unroll")                                                   \
            for (int mt = 0; mt < 4; mt++)                                      \
                mma8(acc[mt][nt],                                               \
                     __float_as_uint(a4[mt][0].z), __float_as_uint(a4[mt][1].z),\
                     __float_as_uint(a4[mt][0].w), __float_as_uint(a4[mt][1].w), b0, b1); \
        }                                                                       \
    }

// ---------------------------------------------------------------------------
// Batched projection GEMM: 3 weight/output variants per launch (z selects).
// dst = f*(A@W^T + bias), head-split layout, always rounded output.
// ---------------------------------------------------------------------------
struct PD {
    const float* W; const float* bias; float* dst;
    int fmode, ostride, ooff, permOut;
};
struct PD3 { PD p[3]; };

__global__ void __launch_bounds__(256,2) gemm_proj(
    const float* __restrict__ A, PD3 d3, const float* __restrict__ alphap, int L)
{
    __shared__ float smA[3][2048];
    __shared__ float smB[3][2048];
    const PD pd = d3.p[blockIdx.z];
    const float* B = pd.W;
    const int tid = threadIdx.x, w = tid >> 5, t = tid & 31;
    const int wm = w & 1, wn = w >> 1;
    const int m0 = blockIdx.y * 128, n0 = blockIdx.x * 128;

    GEMM_MAINLOOP(A, B, 512, 32)

    float f = 1.0f;
    if (pd.fmode){
        float a = 1.0f / (1.0f + expf(-alphap[0]));
        f = (pd.fmode == 1 ? a : 1.0f - a) * 0.125f;
    }
#pragma unroll
    for (int mt = 0; mt < 4; mt++){
#pragma unroll
        for (int nt = 0; nt < 4; nt++){
            int gn = n0 + wn*32 + nt*8 + (t & 3)*2;
            float bi0 = pd.bias[gn], bi1 = pd.bias[gn+1];
            int c = pd.ooff + (gn & 63);
            int bb = c & 15;
            int p0 = (bb & 3)*4 + (bb >> 2);
#pragma unroll
            for (int hh = 0; hh < 2; hh++){
                int gm = m0 + wm*64 + mt*16 + (t >> 2) + hh*8;
                float o0 = rtf(f * (acc[mt][nt][hh*2  ] + bi0));
                float o1 = rtf(f * (acc[mt][nt][hh*2+1] + bi1));
                int b = gm / L, l = gm - b * L;
                size_t rowb = ((size_t)((b*NH + (gn >> 6)) * L + l)) * pd.ostride;
                if (pd.permOut){
                    pd.dst[rowb + (c & ~15) + p0    ] = o0;
                    pd.dst[rowb + (c & ~15) + p0 + 4] = o1;
                } else {
                    *(float2*)&pd.dst[rowb + c] = make_float2(o0, o1);
                }
            }
        }
    }
}

// ---------------------------------------------------------------------------
// Generic TF32 GEMM (scores, out-proj): plain [M,ldo] output.
// ---------------------------------------------------------------------------
__global__ void __launch_bounds__(256,2) gemm_ca(
    const float* __restrict__ A, const float* __restrict__ B,
    const float* __restrict__ bias, float* __restrict__ out,
    int Kdim, long long sA, long long sB, long long sO, int ldo)
{
    __shared__ float smA[3][2048];
    __shared__ float smB[3][2048];
    const int z = blockIdx.z;
    A += (size_t)z * sA;  B += (size_t)z * sB;  out += (size_t)z * sO;

    const int tid = threadIdx.x, w = tid >> 5, t = tid & 31;
    const int wm = w & 1, wn = w >> 1;
    const int m0 = blockIdx.y * 128, n0 = blockIdx.x * 128;
    const int NK = Kdim >> 4;

    GEMM_MAINLOOP(A, B, Kdim, NK)

#pragma unroll
    for (int mt = 0; mt < 4; mt++){
#pragma unroll
        for (int nt = 0; nt < 4; nt++){
            int gn = n0 + wn*32 + nt*8 + (t & 3)*2;
            float bi0 = bias ? bias[gn]   : 0.0f;
            float bi1 = bias ? bias[gn+1] : 0.0f;
#pragma unroll
            for (int hh = 0; hh < 2; hh++){
                int gm = m0 + wm*64 + mt*16 + (t >> 2) + hh*8;
                float o0 = acc[mt][nt][hh*2  ] + bi0;
                float o1 = acc[mt][nt][hh*2+1] + bi1;
                *(float2*)&out[(size_t)gm * ldo + gn] = make_float2(o0, o1);
            }
        }
    }
}

// ---------------------------------------------------------------------------
// Row softmax over 1024 elems, in-place, exact output only (no MUFU).
// ---------------------------------------------------------------------------
__global__ void __launch_bounds__(256) softmax_kernel(
    const float* __restrict__ S, float* __restrict__ out)
{
    const size_t row = blockIdx.x;
    const float* src = S + row * LP;
    float* dst = out + row * LP;
    const int tid = threadIdx.x;

    float4 v = *(const float4*)(src + tid*4);
    float m = fmaxf(fmaxf(v.x, v.y), fmaxf(v.z, v.w));
#pragma unroll
    for (int o = 16; o > 0; o >>= 1) m = fmaxf(m, __shfl_xor_sync(0xFFFFFFFFu, m, o));

    __shared__ float redm[8], reds[8];
    if ((tid & 31) == 0) redm[tid >> 5] = m;
    __syncthreads();
    float rm = redm[0];
#pragma unroll
    for (int i = 1; i < 8; i++) rm = fmaxf(rm, redm[i]);

    float e0 = fexp(v.x - rm), e1 = fexp(v.y - rm);
    float e2 = fexp(v.z - rm), e3 = fexp(v.w - rm);
    float s = e0 + e1 + e2 + e3;
#pragma unroll
    for (int o = 16; o > 0; o >>= 1) s += __shfl_xor_sync(0xFFFFFFFFu, s, o);
    if ((tid & 31) == 0) reds[tid >> 5] = s;
    __syncthreads();
    float tot = 0.0f;
#pragma unroll
    for (int i = 0; i < 8; i++) tot += reds[i];
    float inv = 1.0f / tot;
    *(float4*)(dst + tid*4) = make_float4(e0*inv, e1*inv, e2*inv, e3*inv);
}

// ---------------------------------------------------------------------------
// ctx TF32 cp.async 3-stage (static smem, BK=16), UNpermuted operands.
// A = exact attn (d_out); B = Vd/Vp. Output cd/cp written k-interleaved.
// ---------------------------------------------------------------------------
template<int TRANSA>
__global__ void __launch_bounds__(256) ctx_ca(
    const float* __restrict__ attn, const float* __restrict__ V,
    float* __restrict__ out, int Kdim, int Lout)
{
    const int ASZ = TRANSA ? 2176 : 2560;
    __shared__ float sm[3*2560 + 3*1152];
    float* smB = sm + 3*ASZ;

    const int z = blockIdx.z, b = z >> 3, h = z & 7;
    const int m0 = blockIdx.y * 128;
    const float* A  = attn + (size_t)z * LD * LP;
    const float* Vb = V    + (size_t)z * Kdim * 64;

    const int tid = threadIdx.x, w = tid >> 5, t = tid & 31;
    const int wm = w & 1, wn = w >> 1;
    const int NK = Kdim >> 4;

    auto issue = [&](int kt, int s){
        if (TRANSA == 0){
#pragma unroll
            for (int c = tid; c < 512; c += 256){
                int m = c >> 2, kc = (c & 3) << 2;
                cp16(sm + s*ASZ + m*20 + kc, A + (size_t)(m0+m)*LP + kt*16 + kc);
            }
        } else {
#pragma unroll
            for (int c = tid; c < 512; c += 256){
                int k = c >> 5, m4 = (c & 31) << 2;
                cp16(sm + s*ASZ + k*136 + m4, A + (size_t)(kt*16 + k)*LP + m0 + m4);
            }
        }
        { int c = tid; int k = c >> 4, cc = (c & 15) << 2;
          cp16(smB + s*1152 + k*72 + cc, Vb + (size_t)(kt*16 + k)*64 + cc); }
    };

    issue(0, 0); CP_COMMIT;
    issue(1, 1); CP_COMMIT;

    float acc[4][2][4] = {};
    for (int kt = 0; kt < NK; kt++){
        CP_WAIT1;
        __syncthreads();
        if (kt + 2 < NK) issue(kt + 2, (kt + 2) % 3);
        CP_COMMIT;
        const float* cA = sm + (kt % 3) * ASZ;
        const float* cB = smB + (kt % 3) * 1152;
#pragma unroll
        for (int kk = 0; kk < 2; kk++){
            const int k0 = kk*8 + (t & 3);
            uint32_t af[4][4];
#pragma unroll
            for (int mt = 0; mt < 4; mt++){
                int r = wm*64 + mt*16 + (t >> 2);
                if (TRANSA == 0){
                    af[mt][0] = __float_as_uint(cA[ r     *20 + k0    ]);
                    af[mt][1] = __float_as_uint(cA[(r + 8)*20 + k0    ]);
                    af[mt][2] = __float_as_uint(cA[ r     *20 + k0 + 4]);
                    af[mt][3] = __float_as_uint(cA[(r + 8)*20 + k0 + 4]);
                } else {
                    af[mt][0] = __float_as_uint(cA[ k0     *136 + r    ]);
                    af[mt][1] = __float_as_uint(cA[ k0     *136 + r + 8]);
                    af[mt][2] = __float_as_uint(cA[(k0 + 4)*136 + r    ]);
                    af[mt][3] = __float_as_uint(cA[(k0 + 4)*136 + r + 8]);
                }
            }
#pragma unroll
            for (int nt = 0; nt < 2; nt++){
                int n = wn*16 + nt*8 + (t >> 2);
                uint32_t b0 = __float_as_uint(cB[ k0     *72 + n]);
                uint32_t b1 = __float_as_uint(cB[(k0 + 4)*72 + n]);
#pragma unroll
                for (int mt = 0; mt < 4; mt++)
                    mma8(acc[mt][nt], af[mt][0], af[mt][1], af[mt][2], af[mt][3], b0, b1);
            }
        }
    }

#pragma unroll
    for (int mt = 0; mt < 4; mt++){
#pragma unroll
        for (int nt = 0; nt < 2; nt++){
            int gn = wn*16 + nt*8 + (t & 3)*2;
            int bb = gn & 15;
            int p0 = (bb & 3)*4 + (bb >> 2);
#pragma unroll
            for (int hh = 0; hh < 2; hh++){
                int gm = m0 + wm*64 + mt*16 + (t >> 2) + hh*8;
                size_t base = ((size_t)(b*Lout + gm))*512 + ((h*64 + gn) & ~15);
                out[base + p0    ] = rtf(acc[mt][nt][hh*2  ]);
                out[base + p0 + 4] = rtf(acc[mt][nt][hh*2+1]);
            }
        }
    }
}

// ---------------------------------------------------------------------------
extern "C" void kernel_launch(void* const* d_in, const int* in_sizes, int n_in,
                              void* d_out, int out_size) {
    const float* drug    = (const float*)d_in[0];
    const float* protein = (const float*)d_in[1];
    const float* Wqd = (const float*)d_in[2];  const float* bqd = (const float*)d_in[3];
    const float* Wkp = (const float*)d_in[4];  const float* bkp = (const float*)d_in[5];
    const float* Wvp = (const float*)d_in[6];  const float* bvp = (const float*)d_in[7];
    const float* Wqp = (const float*)d_in[8];  const float* bqp = (const float*)d_in[9];
    const float* Wkd = (const float*)d_in[10]; const float* bkd = (const float*)d_in[11];
    const float* Wvd = (const float*)d_in[12]; const float* bvd = (const float*)d_in[13];
    const float* alpha = (const float*)d_in[14];
    const float* Wod = (const float*)d_in[15]; const float* bod = (const float*)d_in[16];
    const float* Wop = (const float*)d_in[17]; const float* bop = (const float*)d_in[18];

    float* out      = (float*)d_out;
    float* out_attn = out;
    float* out_cd   = out + (size_t)256*LD*LP;
    float* out_cp   = out_cd + (size_t)BB*LD*512;

    float *rd, *rp, *rw, *qkd, *kqp, *vd, *vp, *cd, *cp;
    cudaGetSymbolAddress((void**)&rd,  g_rd);
    cudaGetSymbolAddress((void**)&rp,  g_rp);
    cudaGetSymbolAddress((void**)&rw,  g_W);
    cudaGetSymbolAddress((void**)&qkd, g_QKd);
    cudaGetSymbolAddress((void**)&kqp, g_KQp);
    cudaGetSymbolAddress((void**)&vd,  g_Vd);
    cudaGetSymbolAddress((void**)&vp,  g_Vp);
    cudaGetSymbolAddress((void**)&cd,  g_cd);
    cudaGetSymbolAddress((void**)&cp,  g_cp);

    const int WSZ = 512*512, W4 = WSZ/4;
    // Single merged rounding+interleave launch (10 segments).
    Segs sg;
    const float* Ws[8] = {Wqd, Wkd, Wvd, Wkp, Wqp, Wvp, Wod, Wop};
    sg.s[0] = (const float4*)drug;    sg.d[0] = rd; sg.n4[0] = BB*LD*512/4;
    sg.s[1] = (const float4*)protein; sg.d[1] = rp; sg.n4[1] = BB*LP*512/4;
    for (int i = 0; i < 8; i++){
        sg.s[2+i] = (const float4*)Ws[i];
        sg.d[2+i] = rw + (size_t)i*WSZ;
        sg.n4[2+i] = W4;
    }
    rnd_all<<<dim3(512, 10), 256>>>(sg);

    // Batched projections: drug {Qd,Kd,Vd}, protein {Kp,Qp,Vp}.
    PD3 dd, dp;
    dd.p[0] = {rw + 0*WSZ, bqd, qkd, 1, 128, 0,  1};
    dd.p[1] = {rw + 1*WSZ, bkd, qkd, 2, 128, 64, 1};
    dd.p[2] = {rw + 2*WSZ, bvd, vd,  0, 64,  0,  0};
    dp.p[0] = {rw + 3*WSZ, bkp, kqp, 0, 128, 0,  1};
    dp.p[1] = {rw + 4*WSZ, bqp, kqp, 0, 128, 64, 1};
    dp.p[2] = {rw + 5*WSZ, bvp, vp,  0, 64,  0,  0};
    gemm_proj<<<dim3(4, 64,  3), 256>>>(rd, dd, alpha, LD);
    gemm_proj<<<dim3(4, 256, 3), 256>>>(rp, dp, alpha, LP);

    // Scores: [Qd|Kd]@[Kp|Qp]^T, K=128 (interleaved), exact; softmax in place.
    gemm_ca<<<dim3(8,2,256), 256>>>(qkd, kqp, nullptr, out_attn,
                                    128, (long long)LD*128, (long long)LP*128,
                                    (long long)LD*LP, LP);
    softmax_kernel<<<256*LD, 256>>>(out_attn, out_attn);

    // Contexts (unpermuted attn/V); outputs k-interleaved for out-proj.
    ctx_ca<0><<<dim3(1,2,256), 256>>>(out_attn, vp, cd, LP, LD);
    ctx_ca<1><<<dim3(1,8,256), 256>>>(out_attn, vd, cp, LD, LP);

    // Output projections (exact into d_out, plain layout).
    gemm_ca<<<dim3(4,64),  256>>>(cd, rw + 6*WSZ, bod, out_cd, 512, 0,0,0, 512);
    gemm_ca<<<dim3(4,256), 256>>>(cp, rw + 7*WSZ, bop, out_cp, 512, 0,0,0, 512);
}